// round 9
// baseline (speedup 1.0000x reference)
#include <cuda_runtime.h>
#include <cuda_bf16.h>
#include <cstdint>

// Problem constants
#define NN   32
#define CC   512
#define HWL  3136        // 56*56
#define GG   8
#define LL   64
#define MTOT 100352      // NN*HWL
#define EPSV 1e-4f
#define NPART 128        // 32 n-chunks * 4 k-chunks

#define PADW 68          // floats per smem row (64 + 4 spread)
#define OPOS(o) (8*(o) + 4*((o)>>2))   // word offset of channel-octet o in a row

typedef unsigned long long ull;

// ---------------- scratch (device globals; no allocation allowed) -------------
__device__ float g_pcov[GG][NPART][LL * LL];  // partial Grams (upper tiles only)
__device__ float g_psum[GG][NPART][LL];       // partial channel sums
__device__ float g_mu[CC];
__device__ float g_cov[GG * LL * LL];
__device__ float g_subT[GG * LL * LL];        // whitening subspace, TRANSPOSED [g][k][i] = S[i][k]
__device__ float g_t[CC];                     // t[c] = sum_j S[c][j] * mu[g*64+j]

// ---------------- helpers ------------------------------------------------------
__device__ __forceinline__ uint32_t smem_u32(const void* p) {
    uint32_t a;
    asm("{ .reg .u64 t; cvta.to.shared.u64 t, %1; cvt.u32.u64 %0, t; }" : "=r"(a) : "l"(p));
    return a;
}
__device__ __forceinline__ void cpasync16(uint32_t dst, const void* src) {
    asm volatile("cp.async.ca.shared.global [%0], [%1], 16;" :: "r"(dst), "l"(src) : "memory");
}
#define CP_COMMIT() asm volatile("cp.async.commit_group;" ::: "memory")
#define CP_WAIT0()  asm volatile("cp.async.wait_group 0;" ::: "memory")

__device__ __forceinline__ ull ffma2(ull a, ull b, ull c) {
    ull d;
    asm("fma.rn.f32x2 %0, %1, %2, %3;" : "=l"(d) : "l"(a), "l"(b), "l"(c));
    return d;
}
__device__ __forceinline__ ull dup2(float v) {
    ull d;
    asm("mov.b64 %0, {%1, %1};" : "=l"(d) : "f"(v));
    return d;
}
__device__ __forceinline__ ull pack2(float lo, float hi) {
    ull d;
    asm("mov.b64 %0, {%1, %2};" : "=l"(d) : "f"(lo), "f"(hi));
    return d;
}
__device__ __forceinline__ float2 unpack2(ull v) {
    float lo, hi;
    asm("mov.b64 {%0, %1}, %2;" : "=f"(lo), "=f"(hi) : "l"(v));
    return make_float2(lo, hi);
}

// =============================================================================
// Kernel 1: partial Gram (UPPER TRIANGLE of 8x8 tile grid) + channel sums.
// grid (4 k-chunks, 32 n, 8 g), 64 threads.
//   warp0: 32 lanes = 32 full 8x8 tiles (tiles 0..31 of the triangle).
//   warp1: 32 lanes = the last 4 tiles, each split into 8 column slices (8x1).
// Block FMA stream: 36 ffma2-instructions per k vs 64 for the full Gram.
// Smem: R6's rotated-octet [k][ch] layout (proven). Accumulation order per
// computed entry identical to R6 -> bitwise-identical cov after mirroring.
// =============================================================================
__global__ __launch_bounds__(64) void k_cov_partial(const float* __restrict__ x) {
    const int q = blockIdx.x;           // k-chunk 0..3
    const int n = blockIdx.y;
    const int g = blockIdx.z;
    __shared__ __align__(16) float Xs[64 * PADW];

    const int tid = threadIdx.x, wid = tid >> 5, lane = tid & 31;

    // triangular tile id: warp0 -> lane (0..31); warp1 -> 32 + lane/8 (32..35)
    int tt = (wid == 0) ? lane : (32 + (lane >> 3));
    int ti = 0;
    while (tt >= 8 - ti) { tt -= 8 - ti; ++ti; }
    const int tj = ti + tt;             // tj >= ti
    const int bcol = lane & 7;          // warp1: column within tile

    const int tiles = (q == 0) ? 13 : 12;
    const int k0    = (q == 0) ? 0 : (832 + (q - 1) * 768);
    const float* base = x + ((size_t)n * CC + (size_t)g * LL) * HWL + k0;

    ull acc[4][8];
    #pragma unroll
    for (int p = 0; p < 4; ++p)
        #pragma unroll
        for (int j = 0; j < 8; ++j) acc[p][j] = 0ull;
    float rowsum = 0.f;
    const int ro = tid >> 3, rr = tid & 7;   // rowsum channel = tid

    for (int tI = 0; tI < tiles; ++tI) {
        __syncthreads();
        // load 64 ch x 64 hw, transpose into Xs[k][*] with octet rotation (R6)
        #pragma unroll
        for (int idx = tid; idx < 1024; idx += 64) {
            int r = idx >> 4, c = idx & 15;
            float4 v = *reinterpret_cast<const float4*>(base + (size_t)r * HWL + tI * 64 + c * 4);
            int o = r >> 3, r7 = r & 7;
            float vv[4] = {v.x, v.y, v.z, v.w};
            #pragma unroll
            for (int i = 0; i < 4; ++i) {
                int k = 4 * c + i;
                Xs[k * PADW + OPOS((o + k) & 7) + r7] = vv[i];
            }
        }
        __syncthreads();

        if (wid == 0) {
            #pragma unroll 4
            for (int k = 0; k < 64; ++k) {
                const float* row = Xs + k * PADW;
                rowsum += row[OPOS((ro + k) & 7) + rr];
                int oa = (ti + k) & 7, ob = (tj + k) & 7;
                ulonglong2 A0 = *reinterpret_cast<const ulonglong2*>(row + OPOS(oa));
                ulonglong2 A1 = *reinterpret_cast<const ulonglong2*>(row + OPOS(oa) + 4);
                ull a0 = A0.x, a1 = A0.y, a2 = A1.x, a3 = A1.y;
                float4 b0 = *reinterpret_cast<const float4*>(row + OPOS(ob));
                float4 b1 = *reinterpret_cast<const float4*>(row + OPOS(ob) + 4);
                ull B[8] = {dup2(b0.x), dup2(b0.y), dup2(b0.z), dup2(b0.w),
                            dup2(b1.x), dup2(b1.y), dup2(b1.z), dup2(b1.w)};
                #pragma unroll
                for (int j = 0; j < 8; ++j) {
                    acc[0][j] = ffma2(a0, B[j], acc[0][j]);
                    acc[1][j] = ffma2(a1, B[j], acc[1][j]);
                    acc[2][j] = ffma2(a2, B[j], acc[2][j]);
                    acc[3][j] = ffma2(a3, B[j], acc[3][j]);
                }
            }
        } else {
            #pragma unroll 4
            for (int k = 0; k < 64; ++k) {
                const float* row = Xs + k * PADW;
                rowsum += row[OPOS((ro + k) & 7) + rr];
                int oa = (ti + k) & 7, ob = (tj + k) & 7;
                ulonglong2 A0 = *reinterpret_cast<const ulonglong2*>(row + OPOS(oa));
                ulonglong2 A1 = *reinterpret_cast<const ulonglong2*>(row + OPOS(oa) + 4);
                ull bb = dup2(row[OPOS(ob) + bcol]);
                acc[0][0] = ffma2(A0.x, bb, acc[0][0]);
                acc[1][0] = ffma2(A0.y, bb, acc[1][0]);
                acc[2][0] = ffma2(A1.x, bb, acc[2][0]);
                acc[3][0] = ffma2(A1.y, bb, acc[3][0]);
            }
        }
    }

    const int p = n * 4 + q;
    g_psum[g][p][tid] = rowsum;
    float* outp = &g_pcov[g][p][0];
    if (wid == 0) {
        #pragma unroll
        for (int pp = 0; pp < 4; ++pp) {
            float lo[8], hi[8];
            #pragma unroll
            for (int j = 0; j < 8; ++j) {
                float2 f = unpack2(acc[pp][j]);
                lo[j] = f.x; hi[j] = f.y;
            }
            int r0 = 8 * ti + 2 * pp;
            *reinterpret_cast<float4*>(outp + (size_t)r0 * 64 + 8 * tj)           = make_float4(lo[0], lo[1], lo[2], lo[3]);
            *reinterpret_cast<float4*>(outp + (size_t)r0 * 64 + 8 * tj + 4)       = make_float4(lo[4], lo[5], lo[6], lo[7]);
            *reinterpret_cast<float4*>(outp + (size_t)(r0 + 1) * 64 + 8 * tj)     = make_float4(hi[0], hi[1], hi[2], hi[3]);
            *reinterpret_cast<float4*>(outp + (size_t)(r0 + 1) * 64 + 8 * tj + 4) = make_float4(hi[4], hi[5], hi[6], hi[7]);
        }
    } else {
        #pragma unroll
        for (int pp = 0; pp < 4; ++pp) {
            float2 f = unpack2(acc[pp][0]);
            outp[(size_t)(8 * ti + 2 * pp) * 64 + 8 * tj + bcol]     = f.x;
            outp[(size_t)(8 * ti + 2 * pp + 1) * 64 + 8 * tj + bcol] = f.y;
        }
    }
}

// =============================================================================
// Kernel 2a: reduce channel sums -> mu.  grid 8, 64 threads.
// =============================================================================
__global__ __launch_bounds__(64) void k_mean() {
    const int g = blockIdx.x, i = threadIdx.x;
    float s = 0.f;
    #pragma unroll 4
    for (int p = 0; p < NPART; ++p) s += g_psum[g][p][i];
    g_mu[g * LL + i] = s / (float)MTOT;
}

// =============================================================================
// Kernel 2b: reduce partial Grams -> cov, UPPER tiles only; mirror to lower.
// grid (16,8). Lower-tile threads exit; upper-tile threads write both images.
// =============================================================================
__global__ __launch_bounds__(256) void k_cov_finalize() {
    const int g = blockIdx.y;
    const int e = blockIdx.x * 256 + threadIdx.x;
    const int i = e >> 6, j = e & 63;
    if ((j >> 3) < (i >> 3)) return;          // lower tile: filled by mirror
    float s0 = 0.f, s1 = 0.f, s2 = 0.f, s3 = 0.f;
    #pragma unroll 4
    for (int p = 0; p < NPART; p += 4) {
        s0 += g_pcov[g][p + 0][e];
        s1 += g_pcov[g][p + 1][e];
        s2 += g_pcov[g][p + 2][e];
        s3 += g_pcov[g][p + 3][e];
    }
    float c = ((s0 + s1) + (s2 + s3)) / (float)MTOT - g_mu[g * LL + i] * g_mu[g * LL + j];
    if (i == j) c += EPSV;
    g_cov[g * LL * LL + e] = c;
    if ((j >> 3) > (i >> 3)) g_cov[g * LL * LL + j * 64 + i] = c;
}

// =============================================================================
// Kernel 3: power iteration + deflation (unchanged — matched reference in R1).
// =============================================================================
#define MATVEC64(res, Aarr, vptr) {                                        \
    float y0 = 0.f, y1 = 0.f, y2 = 0.f, y3 = 0.f;                          \
    _Pragma("unroll")                                                      \
    for (int j_ = 0; j_ < 64; j_ += 4) {                                   \
        y0 = fmaf(Aarr[j_ + 0], (vptr)[j_ + 0], y0);                       \
        y1 = fmaf(Aarr[j_ + 1], (vptr)[j_ + 1], y1);                       \
        y2 = fmaf(Aarr[j_ + 2], (vptr)[j_ + 2], y2);                       \
        y3 = fmaf(Aarr[j_ + 3], (vptr)[j_ + 3], y3);                       \
    }                                                                      \
    res = (y0 + y1) + (y2 + y3);                                           \
}

__device__ __forceinline__ float sumsq64(const float* v) {
    float y0 = 0.f, y1 = 0.f, y2 = 0.f, y3 = 0.f;
    #pragma unroll
    for (int j = 0; j < 64; j += 4) {
        y0 = fmaf(v[j + 0], v[j + 0], y0);
        y1 = fmaf(v[j + 1], v[j + 1], y1);
        y2 = fmaf(v[j + 2], v[j + 2], y2);
        y3 = fmaf(v[j + 3], v[j + 3], y3);
    }
    return (y0 + y1) + (y2 + y3);
}
__device__ __forceinline__ float dot64(const float* a, const float* b) {
    float y0 = 0.f, y1 = 0.f, y2 = 0.f, y3 = 0.f;
    #pragma unroll
    for (int j = 0; j < 64; j += 4) {
        y0 = fmaf(a[j + 0], b[j + 0], y0);
        y1 = fmaf(a[j + 1], b[j + 1], y1);
        y2 = fmaf(a[j + 2], b[j + 2], y2);
        y3 = fmaf(a[j + 3], b[j + 3], y3);
    }
    return (y0 + y1) + (y2 + y3);
}

__global__ __launch_bounds__(64) void k_pi(const float* __restrict__ vinit) {
    const int g = blockIdx.x, i = threadIdx.x;
    __shared__ float vs[2][64];
    __shared__ float av[64];

    float A[64], S[64];
    #pragma unroll
    for (int j = 0; j < 64; ++j) {
        A[j] = g_cov[g * LL * LL + i * 64 + j];
        S[j] = 0.f;
    }

    float lam_prev = 0.f;

    for (int e = 0; e < 64; ++e) {
        __syncthreads();
        vs[0][i] = vinit[((size_t)g * LL + e) * LL + i];
        __syncthreads();

        float n2  = sumsq64(vs[0]);
        float inv = 1.f / (sqrtf(n2) + 1e-12f);
        int cur = 0;

        #pragma unroll 1
        for (int it = 0; it < 19; ++it) {
            float y;
            MATVEC64(y, A, vs[cur]);
            y *= inv;
            vs[cur ^ 1][i] = y;
            __syncthreads();
            cur ^= 1;
            n2  = sumsq64(vs[cur]);
            inv = 1.f / (sqrtf(n2) + 1e-12f);
        }

        float vi = vs[cur][i] * inv;
        __syncthreads();
        vs[cur ^ 1][i] = vi;
        __syncthreads();
        cur ^= 1;

        float Avi;
        MATVEC64(Avi, A, vs[cur]);
        av[i] = Avi;
        __syncthreads();

        float vAv = dot64(vs[cur], av);
        float vv  = sumsq64(vs[cur]);
        float lam = vAv / vv;

        if (e > 0 && (lam_prev < lam || lam < EPSV)) break;

        float svi = rsqrtf(lam) * vi;
        #pragma unroll
        for (int j = 0; j < 64; ++j) {
            float vj = vs[cur][j];
            S[j] = fmaf(svi, vj, S[j]);
            A[j] = fmaf(-Avi, vj, A[j]);
        }
        lam_prev = lam;
    }

    #pragma unroll
    for (int j = 0; j < 64; ++j) g_subT[g * LL * LL + j * 64 + i] = S[j];

    float t = 0.f;
    #pragma unroll
    for (int j = 0; j < 64; ++j) t = fmaf(S[j], g_mu[g * LL + j], t);
    g_t[g * LL + i] = t;
}

// =============================================================================
// Kernel 4: apply whitening + affine, packed FFMA2 (R6 verbatim — best known).
// out = (S @ x) * w + (b - t*w).  grid (7 hw-chunks, 32 n, 8 g), 64 threads.
// =============================================================================
#define AP_SMEM_BYTES (3 * 64 * PADW * 4)

__global__ __launch_bounds__(64) void k_apply(const float* __restrict__ x,
                                              const float* __restrict__ wgt,
                                              const float* __restrict__ bia,
                                              float* __restrict__ out) {
    extern __shared__ __align__(16) float smem[];
    float* Ss  = smem;                    // [64][PADW]
    float* Xb0 = smem + 64 * PADW;
    float* Xb1 = smem + 2 * 64 * PADW;

    const int hb = blockIdx.x;            // 0..6 (448 hw each)
    const int n  = blockIdx.y;
    const int g  = blockIdx.z;
    const int tid = threadIdx.x;
    const int cg  = tid >> 4;             // out-channel group (16 ch)
    const int hwg = tid & 15;             // hw group (4 hw)

    // load S^T rows into octet-spread layout (row j = k-index j)
    const float* subT = g_subT + g * 4096;
    #pragma unroll
    for (int idx = tid; idx < 1024; idx += 64) {
        int j = idx >> 4, c = idx & 15;
        float4 v = *reinterpret_cast<const float4*>(subT + j * 64 + c * 4);
        *reinterpret_cast<float4*>(&Ss[j * PADW + OPOS(c >> 1) + 4 * (c & 1)]) = v;
    }

    const float* xbase = x   + ((size_t)n * CC + (size_t)g * LL) * HWL + hb * 448;
    float*       obase = out + ((size_t)n * CC + (size_t)g * LL) * HWL + hb * 448;

    // packed epilogue constants: out = acc * w + (b - t*w), per channel pair
    ull w2[8], q2[8];
    #pragma unroll
    for (int pp = 0; pp < 8; ++pp) {
        int c0 = g * LL + cg * 16 + 2 * pp;
        float wa = wgt[c0], wb = wgt[c0 + 1];
        float qa = bia[c0]     - g_t[c0]     * wa;
        float qb = bia[c0 + 1] - g_t[c0 + 1] * wb;
        w2[pp] = pack2(wa, wb);
        q2[pp] = pack2(qa, qb);
    }

    const uint32_t xs0 = smem_u32(Xb0), xs1 = smem_u32(Xb1);

    #define AP_ISSUE(dst, t) do {                                                   \
        _Pragma("unroll")                                                           \
        for (int idx = tid; idx < 1024; idx += 64) {                                \
            int r = idx >> 4, c = idx & 15;                                         \
            cpasync16((dst) + (uint32_t)(r * PADW + OPOS(c >> 1) + 4 * (c & 1)) * 4,\
                      xbase + (size_t)r * HWL + (t) * 64 + c * 4);                  \
        }                                                                           \
        CP_COMMIT();                                                                \
    } while (0)

    AP_ISSUE(xs0, 0);

    const int bpos = OPOS(hwg >> 1) + 4 * (hwg & 1);
    const int apos0 = OPOS(2 * cg), apos1 = OPOS(2 * cg + 1);

    for (int t = 0; t < 7; ++t) {
        CP_WAIT0();
        __syncthreads();
        if (t < 6) AP_ISSUE((t & 1) ? xs0 : xs1, t + 1);

        const float* Xc = (t & 1) ? Xb1 : Xb0;
        ull acc[8][4];
        #pragma unroll
        for (int p = 0; p < 8; ++p)
            #pragma unroll
            for (int w = 0; w < 4; ++w) acc[p][w] = 0ull;

        #pragma unroll 8
        for (int k = 0; k < 64; ++k) {
            const float* srow = &Ss[k * PADW];
            const float* xrow = &Xc[k * PADW];
            ull a2[8];
            {
                float4 v0 = *reinterpret_cast<const float4*>(srow + apos0);
                float4 v1 = *reinterpret_cast<const float4*>(srow + apos0 + 4);
                float4 v2 = *reinterpret_cast<const float4*>(srow + apos1);
                float4 v3 = *reinterpret_cast<const float4*>(srow + apos1 + 4);
                a2[0] = pack2(v0.x, v0.y); a2[1] = pack2(v0.z, v0.w);
                a2[2] = pack2(v1.x, v1.y); a2[3] = pack2(v1.z, v1.w);
                a2[4] = pack2(v2.x, v2.y); a2[5] = pack2(v2.z, v2.w);
                a2[6] = pack2(v3.x, v3.y); a2[7] = pack2(v3.z, v3.w);
            }
            float4 bv = *reinterpret_cast<const float4*>(xrow + bpos);
            ull bd0 = dup2(bv.x), bd1 = dup2(bv.y), bd2 = dup2(bv.z), bd3 = dup2(bv.w);

            #pragma unroll
            for (int p = 0; p < 8; ++p) {
                acc[p][0] = ffma2(a2[p], bd0, acc[p][0]);
                acc[p][1] = ffma2(a2[p], bd1, acc[p][1]);
                acc[p][2] = ffma2(a2[p], bd2, acc[p][2]);
                acc[p][3] = ffma2(a2[p], bd3, acc[p][3]);
            }
        }

        // packed epilogue + store: out = acc * w + q
        float* op = obase + t * 64 + hwg * 4;
        #pragma unroll
        for (int pp = 0; pp < 8; ++pp) {
            ull r0 = ffma2(acc[pp][0], w2[pp], q2[pp]);
            ull r1 = ffma2(acc[pp][1], w2[pp], q2[pp]);
            ull r2 = ffma2(acc[pp][2], w2[pp], q2[pp]);
            ull r3 = ffma2(acc[pp][3], w2[pp], q2[pp]);
            float2 f0 = unpack2(r0), f1 = unpack2(r1), f2 = unpack2(r2), f3 = unpack2(r3);
            int c0 = cg * 16 + 2 * pp;
            float4 lo4 = make_float4(f0.x, f1.x, f2.x, f3.x);
            float4 hi4 = make_float4(f0.y, f1.y, f2.y, f3.y);
            *reinterpret_cast<float4*>(op + (size_t)c0 * HWL)       = lo4;
            *reinterpret_cast<float4*>(op + (size_t)(c0 + 1) * HWL) = hi4;
        }
        __syncthreads();
    }
    #undef AP_ISSUE
}

// =============================================================================
extern "C" void kernel_launch(void* const* d_in, const int* in_sizes, int n_in,
                              void* d_out, int out_size) {
    const float* x     = (const float*)d_in[0];
    const float* vinit = (const float*)d_in[1];
    const float* wgt   = (const float*)d_in[2];
    const float* bia   = (const float*)d_in[3];
    float* out = (float*)d_out;
    (void)in_sizes; (void)n_in; (void)out_size;

    cudaFuncSetAttribute(k_apply, cudaFuncAttributeMaxDynamicSharedMemorySize, AP_SMEM_BYTES);

    k_cov_partial<<<dim3(4, 32, 8), 64>>>(x);
    k_mean<<<8, 64>>>();
    k_cov_finalize<<<dim3(16, 8), 256>>>();
    k_pi<<<8, 64>>>(vinit);
    k_apply<<<dim3(7, 32, 8), 64, AP_SMEM_BYTES>>>(x, wgt, bia, out);
}

// round 10
// speedup vs baseline: 1.1643x; 1.1643x over previous
#include <cuda_runtime.h>
#include <cuda_bf16.h>
#include <cstdint>

// Problem constants
#define NN   32
#define CC   512
#define HWL  3136        // 56*56
#define GG   8
#define LL   64
#define MTOT 100352      // NN*HWL
#define EPSV 1e-4f
#define NPART 128        // 32 n-chunks * 4 k-chunks

#define PADW 68          // floats per smem row (64 + 4 spread)
#define OPOS(o) (8*(o) + 4*((o)>>2))   // word offset of channel-octet o in a row

typedef unsigned long long ull;

// ---------------- scratch (device globals; no allocation allowed) -------------
__device__ float g_pcov[GG][NPART][LL * LL];  // partial Grams
__device__ float g_psum[GG][NPART][LL];       // partial channel sums
__device__ float g_mu[CC];
__device__ float g_cov[GG * LL * LL];
__device__ float g_subT[GG * LL * LL];        // whitening subspace, TRANSPOSED [g][k][i] = S[i][k]
__device__ float g_t[CC];                     // t[c] = sum_j S[c][j] * mu[g*64+j]

// ---------------- helpers ------------------------------------------------------
__device__ __forceinline__ uint32_t smem_u32(const void* p) {
    uint32_t a;
    asm("{ .reg .u64 t; cvta.to.shared.u64 t, %1; cvt.u32.u64 %0, t; }" : "=r"(a) : "l"(p));
    return a;
}
__device__ __forceinline__ void cpasync16(uint32_t dst, const void* src) {
    asm volatile("cp.async.ca.shared.global [%0], [%1], 16;" :: "r"(dst), "l"(src) : "memory");
}
#define CP_COMMIT() asm volatile("cp.async.commit_group;" ::: "memory")
#define CP_WAIT0()  asm volatile("cp.async.wait_group 0;" ::: "memory")

__device__ __forceinline__ ull ffma2(ull a, ull b, ull c) {
    ull d;
    asm("fma.rn.f32x2 %0, %1, %2, %3;" : "=l"(d) : "l"(a), "l"(b), "l"(c));
    return d;
}
__device__ __forceinline__ ull dup2(float v) {
    ull d;
    asm("mov.b64 %0, {%1, %1};" : "=l"(d) : "f"(v));
    return d;
}
__device__ __forceinline__ ull pack2(float lo, float hi) {
    ull d;
    asm("mov.b64 %0, {%1, %2};" : "=l"(d) : "f"(lo), "f"(hi));
    return d;
}
__device__ __forceinline__ float2 unpack2(ull v) {
    float lo, hi;
    asm("mov.b64 {%0, %1}, %2;" : "=f"(lo), "=f"(hi) : "l"(v));
    return make_float2(lo, hi);
}

// =============================================================================
// Kernel 1: partial Gram + partial channel sums, packed FFMA2 (R6 verbatim).
// grid (4 k-chunks, 32 n, 8 g), 64 threads. Thread = 16 row-ch (8 f32x2 pairs)
// x 4 col-ch; full 64x64 Gram. Rotated-octet smem layout.
// =============================================================================
__global__ __launch_bounds__(64) void k_cov_partial(const float* __restrict__ x) {
    const int q = blockIdx.x;           // k-chunk 0..3
    const int n = blockIdx.y;
    const int g = blockIdx.z;
    __shared__ __align__(16) float Xs[64 * PADW];

    const int tid  = threadIdx.x;
    const int cg   = tid >> 4;          // row-group: 16 channels (8 pairs)
    const int colg = tid & 15;          // col-group: 4 channels

    const int tiles = (q == 0) ? 13 : 12;
    const int k0    = (q == 0) ? 0 : (832 + (q - 1) * 768);
    const float* base = x + ((size_t)n * CC + (size_t)g * LL) * HWL + k0;

    ull acc[8][4];
    #pragma unroll
    for (int p = 0; p < 8; ++p)
        #pragma unroll
        for (int w = 0; w < 4; ++w) acc[p][w] = 0ull;

    float rowsum = 0.f;
    const int ro = tid >> 3, rr = tid & 7;   // rowsum channel octet/slot
    const int bo = colg >> 1, bh = 4 * (colg & 1);

    for (int tI = 0; tI < tiles; ++tI) {
        __syncthreads();
        // load 64 ch x 64 hw, transpose into Xs[k][*] with octet rotation
        #pragma unroll
        for (int idx = tid; idx < 1024; idx += 64) {
            int r = idx >> 4, c = idx & 15;     // channel r, hw-f4 c
            float4 v = *reinterpret_cast<const float4*>(base + (size_t)r * HWL + tI * 64 + c * 4);
            int o = r >> 3, r7 = r & 7;
            float vv[4] = {v.x, v.y, v.z, v.w};
            #pragma unroll
            for (int i = 0; i < 4; ++i) {
                int k = 4 * c + i;
                int op = (o + k) & 7;
                Xs[k * PADW + OPOS(op) + r7] = vv[i];
            }
        }
        __syncthreads();

        #pragma unroll 8
        for (int k = 0; k < 64; ++k) {
            const float* row = &Xs[k * PADW];
            // rowsum for channel tid
            rowsum += row[OPOS((ro + k) & 7) + rr];

            // a: 16 row-channels = octets 2cg, 2cg+1 (rotated)
            int oa0 = (2 * cg + k) & 7, oa1 = (2 * cg + 1 + k) & 7;
            ull a2[8];
            {
                float4 v0 = *reinterpret_cast<const float4*>(row + OPOS(oa0));
                float4 v1 = *reinterpret_cast<const float4*>(row + OPOS(oa0) + 4);
                float4 v2 = *reinterpret_cast<const float4*>(row + OPOS(oa1));
                float4 v3 = *reinterpret_cast<const float4*>(row + OPOS(oa1) + 4);
                a2[0] = pack2(v0.x, v0.y); a2[1] = pack2(v0.z, v0.w);
                a2[2] = pack2(v1.x, v1.y); a2[3] = pack2(v1.z, v1.w);
                a2[4] = pack2(v2.x, v2.y); a2[5] = pack2(v2.z, v2.w);
                a2[6] = pack2(v3.x, v3.y); a2[7] = pack2(v3.z, v3.w);
            }
            // b: 4 col-channels, duplicated into both lanes
            float4 bv = *reinterpret_cast<const float4*>(row + OPOS((bo + k) & 7) + bh);
            ull bd0 = dup2(bv.x), bd1 = dup2(bv.y), bd2 = dup2(bv.z), bd3 = dup2(bv.w);

            #pragma unroll
            for (int p = 0; p < 8; ++p) {
                acc[p][0] = ffma2(a2[p], bd0, acc[p][0]);
                acc[p][1] = ffma2(a2[p], bd1, acc[p][1]);
                acc[p][2] = ffma2(a2[p], bd2, acc[p][2]);
                acc[p][3] = ffma2(a2[p], bd3, acc[p][3]);
            }
        }
    }

    const int p = n * 4 + q;
    g_psum[g][p][tid] = rowsum;
    float* outp = &g_pcov[g][p][0];
    #pragma unroll
    for (int pp = 0; pp < 8; ++pp) {
        float2 f0 = unpack2(acc[pp][0]);
        float2 f1 = unpack2(acc[pp][1]);
        float2 f2 = unpack2(acc[pp][2]);
        float2 f3 = unpack2(acc[pp][3]);
        int i0 = cg * 16 + 2 * pp;
        float4 lo4 = make_float4(f0.x, f1.x, f2.x, f3.x);
        float4 hi4 = make_float4(f0.y, f1.y, f2.y, f3.y);
        *reinterpret_cast<float4*>(outp + (size_t)i0 * 64 + colg * 4)       = lo4;
        *reinterpret_cast<float4*>(outp + (size_t)(i0 + 1) * 64 + colg * 4) = hi4;
    }
}

// =============================================================================
// Kernel 2a: reduce channel sums -> mu.  grid 8, 64 threads.
// =============================================================================
__global__ __launch_bounds__(64) void k_mean() {
    const int g = blockIdx.x, i = threadIdx.x;
    float s = 0.f;
    #pragma unroll 4
    for (int p = 0; p < NPART; ++p) s += g_psum[g][p][i];
    g_mu[g * LL + i] = s / (float)MTOT;
}

// =============================================================================
// Kernel 2b: reduce partial Grams -> cov (with -mu mu^T + eps I). grid (16,8).
// =============================================================================
__global__ __launch_bounds__(256) void k_cov_finalize() {
    const int g = blockIdx.y;
    const int e = blockIdx.x * 256 + threadIdx.x;
    const int i = e >> 6, j = e & 63;
    float s0 = 0.f, s1 = 0.f, s2 = 0.f, s3 = 0.f;
    #pragma unroll 4
    for (int p = 0; p < NPART; p += 4) {
        s0 += g_pcov[g][p + 0][e];
        s1 += g_pcov[g][p + 1][e];
        s2 += g_pcov[g][p + 2][e];
        s3 += g_pcov[g][p + 3][e];
    }
    float c = ((s0 + s1) + (s2 + s3)) / (float)MTOT - g_mu[g * LL + i] * g_mu[g * LL + j];
    if (i == j) c += EPSV;
    g_cov[g * LL * LL + e] = c;
}

// =============================================================================
// Kernel 3: power iteration + deflation (unchanged — matched reference in R1).
// =============================================================================
#define MATVEC64(res, Aarr, vptr) {                                        \
    float y0 = 0.f, y1 = 0.f, y2 = 0.f, y3 = 0.f;                          \
    _Pragma("unroll")                                                      \
    for (int j_ = 0; j_ < 64; j_ += 4) {                                   \
        y0 = fmaf(Aarr[j_ + 0], (vptr)[j_ + 0], y0);                       \
        y1 = fmaf(Aarr[j_ + 1], (vptr)[j_ + 1], y1);                       \
        y2 = fmaf(Aarr[j_ + 2], (vptr)[j_ + 2], y2);                       \
        y3 = fmaf(Aarr[j_ + 3], (vptr)[j_ + 3], y3);                       \
    }                                                                      \
    res = (y0 + y1) + (y2 + y3);                                           \
}

__device__ __forceinline__ float sumsq64(const float* v) {
    float y0 = 0.f, y1 = 0.f, y2 = 0.f, y3 = 0.f;
    #pragma unroll
    for (int j = 0; j < 64; j += 4) {
        y0 = fmaf(v[j + 0], v[j + 0], y0);
        y1 = fmaf(v[j + 1], v[j + 1], y1);
        y2 = fmaf(v[j + 2], v[j + 2], y2);
        y3 = fmaf(v[j + 3], v[j + 3], y3);
    }
    return (y0 + y1) + (y2 + y3);
}
__device__ __forceinline__ float dot64(const float* a, const float* b) {
    float y0 = 0.f, y1 = 0.f, y2 = 0.f, y3 = 0.f;
    #pragma unroll
    for (int j = 0; j < 64; j += 4) {
        y0 = fmaf(a[j + 0], b[j + 0], y0);
        y1 = fmaf(a[j + 1], b[j + 1], y1);
        y2 = fmaf(a[j + 2], b[j + 2], y2);
        y3 = fmaf(a[j + 3], b[j + 3], y3);
    }
    return (y0 + y1) + (y2 + y3);
}

__global__ __launch_bounds__(64) void k_pi(const float* __restrict__ vinit) {
    const int g = blockIdx.x, i = threadIdx.x;
    __shared__ float vs[2][64];
    __shared__ float av[64];

    float A[64], S[64];
    #pragma unroll
    for (int j = 0; j < 64; ++j) {
        A[j] = g_cov[g * LL * LL + i * 64 + j];
        S[j] = 0.f;
    }

    float lam_prev = 0.f;

    for (int e = 0; e < 64; ++e) {
        __syncthreads();
        vs[0][i] = vinit[((size_t)g * LL + e) * LL + i];
        __syncthreads();

        float n2  = sumsq64(vs[0]);
        float inv = 1.f / (sqrtf(n2) + 1e-12f);
        int cur = 0;

        #pragma unroll 1
        for (int it = 0; it < 19; ++it) {
            float y;
            MATVEC64(y, A, vs[cur]);
            y *= inv;
            vs[cur ^ 1][i] = y;
            __syncthreads();
            cur ^= 1;
            n2  = sumsq64(vs[cur]);
            inv = 1.f / (sqrtf(n2) + 1e-12f);
        }

        float vi = vs[cur][i] * inv;
        __syncthreads();
        vs[cur ^ 1][i] = vi;
        __syncthreads();
        cur ^= 1;

        float Avi;
        MATVEC64(Avi, A, vs[cur]);
        av[i] = Avi;
        __syncthreads();

        float vAv = dot64(vs[cur], av);
        float vv  = sumsq64(vs[cur]);
        float lam = vAv / vv;

        if (e > 0 && (lam_prev < lam || lam < EPSV)) break;

        float svi = rsqrtf(lam) * vi;
        #pragma unroll
        for (int j = 0; j < 64; ++j) {
            float vj = vs[cur][j];
            S[j] = fmaf(svi, vj, S[j]);
            A[j] = fmaf(-Avi, vj, A[j]);
        }
        lam_prev = lam;
    }

    #pragma unroll
    for (int j = 0; j < 64; ++j) g_subT[g * LL * LL + j * 64 + i] = S[j];

    float t = 0.f;
    #pragma unroll
    for (int j = 0; j < 64; ++j) t = fmaf(S[j], g_mu[g * LL + j], t);
    g_t[g * LL + i] = t;
}

// =============================================================================
// Kernel 4: apply whitening + affine, packed FFMA2, 128 threads (16 warps/SM).
// out = (S @ x) * w + (b - t*w).  grid (7 hw-chunks, 32 n, 8 g).
// Thread = 16 out-ch (8 pairs, cg = tid>>5 uniform per warp -> broadcast A
// loads) x 2 hw (pair p = tid&31). Same smem as R6 (4 blocks/SM) but 2x warps
// for latency hiding on the FFMA2 stream.
// =============================================================================
#define AP_SMEM_BYTES (3 * 64 * PADW * 4)

__global__ __launch_bounds__(128) void k_apply(const float* __restrict__ x,
                                               const float* __restrict__ wgt,
                                               const float* __restrict__ bia,
                                               float* __restrict__ out) {
    extern __shared__ __align__(16) float smem[];
    float* Ss  = smem;                    // [64][PADW]
    float* Xb0 = smem + 64 * PADW;
    float* Xb1 = smem + 2 * 64 * PADW;

    const int hb = blockIdx.x;            // 0..6 (448 hw each)
    const int n  = blockIdx.y;
    const int g  = blockIdx.z;
    const int tid = threadIdx.x;
    const int cg  = tid >> 5;             // out-channel group (16 ch); uniform per warp
    const int hp  = tid & 31;             // hw pair index -> hw 2hp, 2hp+1

    // load S^T rows into octet-spread layout (row j = k-index j)
    const float* subT = g_subT + g * 4096;
    #pragma unroll
    for (int idx = tid; idx < 1024; idx += 128) {
        int j = idx >> 4, c = idx & 15;
        float4 v = *reinterpret_cast<const float4*>(subT + j * 64 + c * 4);
        *reinterpret_cast<float4*>(&Ss[j * PADW + OPOS(c >> 1) + 4 * (c & 1)]) = v;
    }

    const float* xbase = x   + ((size_t)n * CC + (size_t)g * LL) * HWL + hb * 448;
    float*       obase = out + ((size_t)n * CC + (size_t)g * LL) * HWL + hb * 448;

    // packed epilogue constants: out = acc * w + (b - t*w), per channel pair
    ull w2[8], q2[8];
    #pragma unroll
    for (int pp = 0; pp < 8; ++pp) {
        int c0 = g * LL + cg * 16 + 2 * pp;
        float wa = wgt[c0], wb = wgt[c0 + 1];
        float qa = bia[c0]     - g_t[c0]     * wa;
        float qb = bia[c0 + 1] - g_t[c0 + 1] * wb;
        w2[pp] = pack2(wa, wb);
        q2[pp] = pack2(qa, qb);
    }

    const uint32_t xs0 = smem_u32(Xb0), xs1 = smem_u32(Xb1);

    #define AP_ISSUE(dst, t) do {                                                   \
        _Pragma("unroll")                                                           \
        for (int idx = tid; idx < 1024; idx += 128) {                               \
            int r = idx >> 4, c = idx & 15;                                         \
            cpasync16((dst) + (uint32_t)(r * PADW + OPOS(c >> 1) + 4 * (c & 1)) * 4,\
                      xbase + (size_t)r * HWL + (t) * 64 + c * 4);                  \
        }                                                                           \
        CP_COMMIT();                                                                \
    } while (0)

    AP_ISSUE(xs0, 0);

    // X float at logical hw position h lives at OPOS(h>>3) + (h&7)
    const int bpos  = OPOS(hp >> 2) + 2 * (hp & 3);   // pair (2hp, 2hp+1)
    const int apos0 = OPOS(2 * cg), apos1 = OPOS(2 * cg + 1);

    for (int t = 0; t < 7; ++t) {
        CP_WAIT0();
        __syncthreads();
        if (t < 6) AP_ISSUE((t & 1) ? xs0 : xs1, t + 1);

        const float* Xc = (t & 1) ? Xb1 : Xb0;
        ull acc[8][2];
        #pragma unroll
        for (int p = 0; p < 8; ++p) { acc[p][0] = 0ull; acc[p][1] = 0ull; }

        #pragma unroll 8
        for (int k = 0; k < 64; ++k) {
            const float* srow = &Ss[k * PADW];
            const float* xrow = &Xc[k * PADW];
            ull a2[8];
            {
                float4 v0 = *reinterpret_cast<const float4*>(srow + apos0);
                float4 v1 = *reinterpret_cast<const float4*>(srow + apos0 + 4);
                float4 v2 = *reinterpret_cast<const float4*>(srow + apos1);
                float4 v3 = *reinterpret_cast<const float4*>(srow + apos1 + 4);
                a2[0] = pack2(v0.x, v0.y); a2[1] = pack2(v0.z, v0.w);
                a2[2] = pack2(v1.x, v1.y); a2[3] = pack2(v1.z, v1.w);
                a2[4] = pack2(v2.x, v2.y); a2[5] = pack2(v2.z, v2.w);
                a2[6] = pack2(v3.x, v3.y); a2[7] = pack2(v3.z, v3.w);
            }
            float2 bv = *reinterpret_cast<const float2*>(xrow + bpos);
            ull bd0 = dup2(bv.x), bd1 = dup2(bv.y);

            #pragma unroll
            for (int p = 0; p < 8; ++p) {
                acc[p][0] = ffma2(a2[p], bd0, acc[p][0]);
                acc[p][1] = ffma2(a2[p], bd1, acc[p][1]);
            }
        }

        // packed epilogue + store: out = acc * w + q; 2 hw columns per thread
        float* op = obase + t * 64 + 2 * hp;
        #pragma unroll
        for (int pp = 0; pp < 8; ++pp) {
            ull r0 = ffma2(acc[pp][0], w2[pp], q2[pp]);
            ull r1 = ffma2(acc[pp][1], w2[pp], q2[pp]);
            float2 f0 = unpack2(r0), f1 = unpack2(r1);
            int c0 = cg * 16 + 2 * pp;
            *reinterpret_cast<float2*>(op + (size_t)c0 * HWL)       = make_float2(f0.x, f1.x);
            *reinterpret_cast<float2*>(op + (size_t)(c0 + 1) * HWL) = make_float2(f0.y, f1.y);
        }
        __syncthreads();
    }
    #undef AP_ISSUE
}

// =============================================================================
extern "C" void kernel_launch(void* const* d_in, const int* in_sizes, int n_in,
                              void* d_out, int out_size) {
    const float* x     = (const float*)d_in[0];
    const float* vinit = (const float*)d_in[1];
    const float* wgt   = (const float*)d_in[2];
    const float* bia   = (const float*)d_in[3];
    float* out = (float*)d_out;
    (void)in_sizes; (void)n_in; (void)out_size;

    cudaFuncSetAttribute(k_apply, cudaFuncAttributeMaxDynamicSharedMemorySize, AP_SMEM_BYTES);

    k_cov_partial<<<dim3(4, 32, 8), 64>>>(x);
    k_mean<<<8, 64>>>();
    k_cov_finalize<<<dim3(16, 8), 256>>>();
    k_pi<<<8, 64>>>(vinit);
    k_apply<<<dim3(7, 32, 8), 128, AP_SMEM_BYTES>>>(x, wgt, bia, out);
}

// round 11
// speedup vs baseline: 1.5049x; 1.2926x over previous
#include <cuda_runtime.h>
#include <cstdint>

// Problem constants
#define NN   32
#define CC   512
#define HWL  3136        // 56*56
#define GG   8
#define LL   64
#define MTOT 100352      // NN*HWL
#define EPSV 1e-4f
#define NPART 128        // 32 n-chunks * 4 k-chunks
#define RL   68          // smem row stride (floats) for [m][k]-style arrays
#define RLX  72          // smem row stride for apply's X [k][n] (72 mod 32 == 8)

// ---------------- scratch (device globals; no allocation allowed) -------------
__device__ float g_pcov[GG][NPART][LL * LL];  // partial Grams
__device__ float g_psum[GG][NPART][LL];       // partial channel sums
__device__ float g_mu[CC];
__device__ float g_cov[GG * LL * LL];
__device__ float g_subT[GG * LL * LL];        // whitening subspace, TRANSPOSED [g][k][i] = S[i][k]
__device__ float g_t[CC];                     // t[c] = sum_j S[c][j] * mu[g*64+j]

// ---------------- helpers ------------------------------------------------------
// m16n8k8 tf32 MMA, fp32 accumulate (sm_80 PTX -> legal for compute_103 family)
__device__ __forceinline__ void mma_tf32(float c[4],
                                         uint32_t a0, uint32_t a1, uint32_t a2, uint32_t a3,
                                         uint32_t b0, uint32_t b1) {
    asm volatile(
        "mma.sync.aligned.m16n8k8.row.col.f32.tf32.tf32.f32 "
        "{%0,%1,%2,%3}, {%4,%5,%6,%7}, {%8,%9}, {%0,%1,%2,%3};"
        : "+f"(c[0]), "+f"(c[1]), "+f"(c[2]), "+f"(c[3])
        : "r"(a0), "r"(a1), "r"(a2), "r"(a3), "r"(b0), "r"(b1));
}
// tf32 "hi" part: truncate mantissa to the 13 bits HW keeps. lo = x - hi (exact).
__device__ __forceinline__ float hi_tf32(float x) {
    return __uint_as_float(__float_as_uint(x) & 0xFFFFE000u);
}
__device__ __forceinline__ uint32_t fbits(float x) { return __float_as_uint(x); }

// =============================================================================
// Kernel 1: partial Gram + partial channel sums via 3xTF32 tensor MMA.
// grid (4 k-chunks, 32 n, 8 g), 128 threads (4 warps).
// C[64,64] = X Xt: A = X[m=ch][k=hw], B: b(k,n) = X[n][k] — both read the
// natural [ch][hw] smem tile (stride RL=68, conflict-free lane maps).
// Warp w owns m-strip [16w, 16w+16); per k8-step: 8 A-LDS + 32 B-LDS + 24 MMA.
// =============================================================================
__global__ __launch_bounds__(128) void k_cov_partial(const float* __restrict__ x) {
    const int q = blockIdx.x;           // k-chunk 0..3
    const int n = blockIdx.y;
    const int g = blockIdx.z;
    __shared__ __align__(16) float Xhi[64 * RL];
    __shared__ __align__(16) float Xlo[64 * RL];

    const int tid = threadIdx.x, wid = tid >> 5, lane = tid & 31;
    const int r = lane >> 2, c = lane & 3;     // fragment row/col groups
    const int mbase = wid * 16;
    const int lr = tid >> 4, lc = tid & 15;    // loader row/col

    const int tiles = (q == 0) ? 13 : 12;
    const int k0    = (q == 0) ? 0 : (832 + (q - 1) * 768);
    const float* base = x + ((size_t)n * CC + (size_t)g * LL) * HWL + k0;

    float acc[8][4];
    #pragma unroll
    for (int t = 0; t < 8; ++t)
        #pragma unroll
        for (int j = 0; j < 4; ++j) acc[t][j] = 0.f;
    float psum[8];
    #pragma unroll
    for (int j = 0; j < 8; ++j) psum[j] = 0.f;

    float4 regs[8];
    #pragma unroll
    for (int j = 0; j < 8; ++j)
        regs[j] = *reinterpret_cast<const float4*>(base + (size_t)(lr + 8 * j) * HWL + lc * 4);

    for (int tI = 0; tI < tiles; ++tI) {
        __syncthreads();
        // split + store + rowsum partials
        #pragma unroll
        for (int j = 0; j < 8; ++j) {
            float4 v = regs[j];
            psum[j] += (v.x + v.y) + (v.z + v.w);
            float4 h, l;
            h.x = hi_tf32(v.x); h.y = hi_tf32(v.y); h.z = hi_tf32(v.z); h.w = hi_tf32(v.w);
            l.x = v.x - h.x; l.y = v.y - h.y; l.z = v.z - h.z; l.w = v.w - h.w;
            *reinterpret_cast<float4*>(Xhi + (lr + 8 * j) * RL + lc * 4) = h;
            *reinterpret_cast<float4*>(Xlo + (lr + 8 * j) * RL + lc * 4) = l;
        }
        __syncthreads();
        if (tI + 1 < tiles) {
            const float* b2 = base + (tI + 1) * 64;
            #pragma unroll
            for (int j = 0; j < 8; ++j)
                regs[j] = *reinterpret_cast<const float4*>(b2 + (size_t)(lr + 8 * j) * HWL + lc * 4);
        }

        #pragma unroll
        for (int ks = 0; ks < 8; ++ks) {
            const int ka = 8 * ks + c;
            uint32_t ah0 = fbits(Xhi[(mbase + r) * RL + ka]);
            uint32_t ah1 = fbits(Xhi[(mbase + r + 8) * RL + ka]);
            uint32_t ah2 = fbits(Xhi[(mbase + r) * RL + ka + 4]);
            uint32_t ah3 = fbits(Xhi[(mbase + r + 8) * RL + ka + 4]);
            uint32_t al0 = fbits(Xlo[(mbase + r) * RL + ka]);
            uint32_t al1 = fbits(Xlo[(mbase + r + 8) * RL + ka]);
            uint32_t al2 = fbits(Xlo[(mbase + r) * RL + ka + 4]);
            uint32_t al3 = fbits(Xlo[(mbase + r + 8) * RL + ka + 4]);
            #pragma unroll
            for (int nt = 0; nt < 8; ++nt) {
                const int brow = nt * 8 + r;
                uint32_t bh0 = fbits(Xhi[brow * RL + ka]);
                uint32_t bh1 = fbits(Xhi[brow * RL + ka + 4]);
                uint32_t bl0 = fbits(Xlo[brow * RL + ka]);
                uint32_t bl1 = fbits(Xlo[brow * RL + ka + 4]);
                mma_tf32(acc[nt], ah0, ah1, ah2, ah3, bh0, bh1);
                mma_tf32(acc[nt], ah0, ah1, ah2, ah3, bl0, bl1);
                mma_tf32(acc[nt], al0, al1, al2, al3, bh0, bh1);
            }
        }
    }

    // rowsum reduction (reuse Xhi as [64][16] scratch)
    __syncthreads();
    #pragma unroll
    for (int j = 0; j < 8; ++j) Xhi[(lr + 8 * j) * 16 + lc] = psum[j];
    __syncthreads();
    const int p = n * 4 + q;
    if (tid < 64) {
        float s = 0.f;
        #pragma unroll
        for (int k = 0; k < 16; ++k) s += Xhi[tid * 16 + k];
        g_psum[g][p][tid] = s;
    }
    float* outp = &g_pcov[g][p][0];
    #pragma unroll
    for (int nt = 0; nt < 8; ++nt) {
        int col = nt * 8 + 2 * c;
        *reinterpret_cast<float2*>(outp + (size_t)(mbase + r) * 64 + col)     = make_float2(acc[nt][0], acc[nt][1]);
        *reinterpret_cast<float2*>(outp + (size_t)(mbase + r + 8) * 64 + col) = make_float2(acc[nt][2], acc[nt][3]);
    }
}

// =============================================================================
// Kernel 2a: reduce channel sums -> mu.  grid 8, 64 threads.
// =============================================================================
__global__ __launch_bounds__(64) void k_mean() {
    const int g = blockIdx.x, i = threadIdx.x;
    float s = 0.f;
    #pragma unroll 4
    for (int p = 0; p < NPART; ++p) s += g_psum[g][p][i];
    g_mu[g * LL + i] = s / (float)MTOT;
}

// =============================================================================
// Kernel 2b: reduce partial Grams -> cov (with -mu mu^T + eps I). grid (16,8).
// =============================================================================
__global__ __launch_bounds__(256) void k_cov_finalize() {
    const int g = blockIdx.y;
    const int e = blockIdx.x * 256 + threadIdx.x;
    const int i = e >> 6, j = e & 63;
    float s0 = 0.f, s1 = 0.f, s2 = 0.f, s3 = 0.f;
    #pragma unroll 4
    for (int p = 0; p < NPART; p += 4) {
        s0 += g_pcov[g][p + 0][e];
        s1 += g_pcov[g][p + 1][e];
        s2 += g_pcov[g][p + 2][e];
        s3 += g_pcov[g][p + 3][e];
    }
    float c = ((s0 + s1) + (s2 + s3)) / (float)MTOT - g_mu[g * LL + i] * g_mu[g * LL + j];
    if (i == j) c += EPSV;
    g_cov[g * LL * LL + e] = c;
}

// =============================================================================
// Kernel 3: power iteration + deflation (unchanged — matched reference in R1).
// =============================================================================
#define MATVEC64(res, Aarr, vptr) {                                        \
    float y0 = 0.f, y1 = 0.f, y2 = 0.f, y3 = 0.f;                          \
    _Pragma("unroll")                                                      \
    for (int j_ = 0; j_ < 64; j_ += 4) {                                   \
        y0 = fmaf(Aarr[j_ + 0], (vptr)[j_ + 0], y0);                       \
        y1 = fmaf(Aarr[j_ + 1], (vptr)[j_ + 1], y1);                       \
        y2 = fmaf(Aarr[j_ + 2], (vptr)[j_ + 2], y2);                       \
        y3 = fmaf(Aarr[j_ + 3], (vptr)[j_ + 3], y3);                       \
    }                                                                      \
    res = (y0 + y1) + (y2 + y3);                                           \
}

__device__ __forceinline__ float sumsq64(const float* v) {
    float y0 = 0.f, y1 = 0.f, y2 = 0.f, y3 = 0.f;
    #pragma unroll
    for (int j = 0; j < 64; j += 4) {
        y0 = fmaf(v[j + 0], v[j + 0], y0);
        y1 = fmaf(v[j + 1], v[j + 1], y1);
        y2 = fmaf(v[j + 2], v[j + 2], y2);
        y3 = fmaf(v[j + 3], v[j + 3], y3);
    }
    return (y0 + y1) + (y2 + y3);
}
__device__ __forceinline__ float dot64(const float* a, const float* b) {
    float y0 = 0.f, y1 = 0.f, y2 = 0.f, y3 = 0.f;
    #pragma unroll
    for (int j = 0; j < 64; j += 4) {
        y0 = fmaf(a[j + 0], b[j + 0], y0);
        y1 = fmaf(a[j + 1], b[j + 1], y1);
        y2 = fmaf(a[j + 2], b[j + 2], y2);
        y3 = fmaf(a[j + 3], b[j + 3], y3);
    }
    return (y0 + y1) + (y2 + y3);
}

__global__ __launch_bounds__(64) void k_pi(const float* __restrict__ vinit) {
    const int g = blockIdx.x, i = threadIdx.x;
    __shared__ float vs[2][64];
    __shared__ float av[64];

    float A[64], S[64];
    #pragma unroll
    for (int j = 0; j < 64; ++j) {
        A[j] = g_cov[g * LL * LL + i * 64 + j];
        S[j] = 0.f;
    }

    float lam_prev = 0.f;

    for (int e = 0; e < 64; ++e) {
        __syncthreads();
        vs[0][i] = vinit[((size_t)g * LL + e) * LL + i];
        __syncthreads();

        float n2  = sumsq64(vs[0]);
        float inv = 1.f / (sqrtf(n2) + 1e-12f);
        int cur = 0;

        #pragma unroll 1
        for (int it = 0; it < 19; ++it) {
            float y;
            MATVEC64(y, A, vs[cur]);
            y *= inv;
            vs[cur ^ 1][i] = y;
            __syncthreads();
            cur ^= 1;
            n2  = sumsq64(vs[cur]);
            inv = 1.f / (sqrtf(n2) + 1e-12f);
        }

        float vi = vs[cur][i] * inv;
        __syncthreads();
        vs[cur ^ 1][i] = vi;
        __syncthreads();
        cur ^= 1;

        float Avi;
        MATVEC64(Avi, A, vs[cur]);
        av[i] = Avi;
        __syncthreads();

        float vAv = dot64(vs[cur], av);
        float vv  = sumsq64(vs[cur]);
        float lam = vAv / vv;

        if (e > 0 && (lam_prev < lam || lam < EPSV)) break;

        float svi = rsqrtf(lam) * vi;
        #pragma unroll
        for (int j = 0; j < 64; ++j) {
            float vj = vs[cur][j];
            S[j] = fmaf(svi, vj, S[j]);
            A[j] = fmaf(-Avi, vj, A[j]);
        }
        lam_prev = lam;
    }

    #pragma unroll
    for (int j = 0; j < 64; ++j) g_subT[g * LL * LL + j * 64 + i] = S[j];

    float t = 0.f;
    #pragma unroll
    for (int j = 0; j < 64; ++j) t = fmaf(S[j], g_mu[g * LL + j], t);
    g_t[g * LL + i] = t;
}

// =============================================================================
// Kernel 4: apply whitening + affine via 3xTF32 tensor MMA.
// out = (S @ x) * w + (b - t*w).  grid (7 hw-chunks, 32 n, 8 g), 128 threads.
// A = S stored [m][k] stride RL (transposed from g_subT at load, one-time);
// B = X stored [k][n] stride RLX=72 (natural rows; 72 mod 32 = 8 makes the
// b-fragment lane map 8c+r conflict-free). Warp w owns out-channels [16w,16w+16).
// =============================================================================
#define AP_SMEM_BYTES ((2 * 64 * RL + 2 * 64 * RLX) * 4)

__global__ __launch_bounds__(128) void k_apply(const float* __restrict__ x,
                                               const float* __restrict__ wgt,
                                               const float* __restrict__ bia,
                                               float* __restrict__ out) {
    extern __shared__ __align__(16) float smem[];
    float* Shi = smem;
    float* Slo = smem + 64 * RL;
    float* Xh  = smem + 2 * 64 * RL;
    float* Xl  = Xh + 64 * RLX;

    const int hb = blockIdx.x;            // 0..6 (448 hw each)
    const int n  = blockIdx.y;
    const int g  = blockIdx.z;
    const int tid = threadIdx.x, wid = tid >> 5, lane = tid & 31;
    const int r = lane >> 2, c = lane & 3;
    const int mbase = wid * 16;
    const int lr = tid >> 4, lc = tid & 15;

    // load S transposed into [m][k] (hi/lo): g_subT[g][k*64+m] = S[m][k]
    const float* subT = g_subT + g * 4096;
    for (int idx = tid; idx < 1024; idx += 128) {
        int k = idx >> 4, m4 = idx & 15;
        float4 v = *reinterpret_cast<const float4*>(subT + k * 64 + m4 * 4);
        float h0 = hi_tf32(v.x), h1 = hi_tf32(v.y), h2 = hi_tf32(v.z), h3 = hi_tf32(v.w);
        Shi[(4 * m4 + 0) * RL + k] = h0;  Slo[(4 * m4 + 0) * RL + k] = v.x - h0;
        Shi[(4 * m4 + 1) * RL + k] = h1;  Slo[(4 * m4 + 1) * RL + k] = v.y - h1;
        Shi[(4 * m4 + 2) * RL + k] = h2;  Slo[(4 * m4 + 2) * RL + k] = v.z - h2;
        Shi[(4 * m4 + 3) * RL + k] = h3;  Slo[(4 * m4 + 3) * RL + k] = v.w - h3;
    }

    const float* xbase = x   + ((size_t)n * CC + (size_t)g * LL) * HWL + hb * 448;
    float*       obase = out + ((size_t)n * CC + (size_t)g * LL) * HWL + hb * 448;

    // per-thread epilogue constants (channels mbase+r and mbase+r+8)
    const int gc0 = g * LL + mbase + r, gc1 = gc0 + 8;
    const float w0 = wgt[gc0], w1 = wgt[gc1];
    const float q0 = bia[gc0] - g_t[gc0] * w0;
    const float q1 = bia[gc1] - g_t[gc1] * w1;

    float4 regs[8];
    #pragma unroll
    for (int j = 0; j < 8; ++j)
        regs[j] = *reinterpret_cast<const float4*>(xbase + (size_t)(lr + 8 * j) * HWL + lc * 4);

    for (int t = 0; t < 7; ++t) {
        __syncthreads();
        #pragma unroll
        for (int j = 0; j < 8; ++j) {
            float4 v = regs[j];
            float4 h, l;
            h.x = hi_tf32(v.x); h.y = hi_tf32(v.y); h.z = hi_tf32(v.z); h.w = hi_tf32(v.w);
            l.x = v.x - h.x; l.y = v.y - h.y; l.z = v.z - h.z; l.w = v.w - h.w;
            *reinterpret_cast<float4*>(Xh + (lr + 8 * j) * RLX + lc * 4) = h;
            *reinterpret_cast<float4*>(Xl + (lr + 8 * j) * RLX + lc * 4) = l;
        }
        __syncthreads();
        if (t < 6) {
            const float* b2 = xbase + (t + 1) * 64;
            #pragma unroll
            for (int j = 0; j < 8; ++j)
                regs[j] = *reinterpret_cast<const float4*>(b2 + (size_t)(lr + 8 * j) * HWL + lc * 4);
        }

        float acc[8][4];
        #pragma unroll
        for (int nt = 0; nt < 8; ++nt)
            #pragma unroll
            for (int j = 0; j < 4; ++j) acc[nt][j] = 0.f;

        #pragma unroll
        for (int ks = 0; ks < 8; ++ks) {
            const int ka = 8 * ks + c;
            uint32_t ah0 = fbits(Shi[(mbase + r) * RL + ka]);
            uint32_t ah1 = fbits(Shi[(mbase + r + 8) * RL + ka]);
            uint32_t ah2 = fbits(Shi[(mbase + r) * RL + ka + 4]);
            uint32_t ah3 = fbits(Shi[(mbase + r + 8) * RL + ka + 4]);
            uint32_t al0 = fbits(Slo[(mbase + r) * RL + ka]);
            uint32_t al1 = fbits(Slo[(mbase + r + 8) * RL + ka]);
            uint32_t al2 = fbits(Slo[(mbase + r) * RL + ka + 4]);
            uint32_t al3 = fbits(Slo[(mbase + r + 8) * RL + ka + 4]);
            #pragma unroll
            for (int nt = 0; nt < 8; ++nt) {
                const int bn = nt * 8 + r;
                uint32_t bh0 = fbits(Xh[ka * RLX + bn]);
                uint32_t bh1 = fbits(Xh[(ka + 4) * RLX + bn]);
                uint32_t bl0 = fbits(Xl[ka * RLX + bn]);
                uint32_t bl1 = fbits(Xl[(ka + 4) * RLX + bn]);
                mma_tf32(acc[nt], ah0, ah1, ah2, ah3, bh0, bh1);
                mma_tf32(acc[nt], ah0, ah1, ah2, ah3, bl0, bl1);
                mma_tf32(acc[nt], al0, al1, al2, al3, bh0, bh1);
            }
        }

        // epilogue: out = acc * w + q
        float* op = obase + t * 64;
        #pragma unroll
        for (int nt = 0; nt < 8; ++nt) {
            int col = nt * 8 + 2 * c;
            float2 v0 = make_float2(fmaf(acc[nt][0], w0, q0), fmaf(acc[nt][1], w0, q0));
            float2 v1 = make_float2(fmaf(acc[nt][2], w1, q1), fmaf(acc[nt][3], w1, q1));
            *reinterpret_cast<float2*>(op + (size_t)(mbase + r) * HWL + col)     = v0;
            *reinterpret_cast<float2*>(op + (size_t)(mbase + r + 8) * HWL + col) = v1;
        }
    }
}

// =============================================================================
extern "C" void kernel_launch(void* const* d_in, const int* in_sizes, int n_in,
                              void* d_out, int out_size) {
    const float* x     = (const float*)d_in[0];
    const float* vinit = (const float*)d_in[1];
    const float* wgt   = (const float*)d_in[2];
    const float* bia   = (const float*)d_in[3];
    float* out = (float*)d_out;
    (void)in_sizes; (void)n_in; (void)out_size;

    cudaFuncSetAttribute(k_apply, cudaFuncAttributeMaxDynamicSharedMemorySize, AP_SMEM_BYTES);

    k_cov_partial<<<dim3(4, 32, 8), 128>>>(x);
    k_mean<<<8, 64>>>();
    k_cov_finalize<<<dim3(16, 8), 256>>>();
    k_pi<<<8, 64>>>(vinit);
    k_apply<<<dim3(7, 32, 8), 128, AP_SMEM_BYTES>>>(x, wgt, bia, out);
}